// round 1
// baseline (speedup 1.0000x reference)
#include <cuda_runtime.h>
#include <math.h>

// Problem constants (fixed by the reference)
#define B_SZ 16384
#define N_SZ 1024
#define I_SZ 128
#define O_SZ 64
#define REFRACT 0.9f

// GEMM tiling
#define BM 128
#define BN 64
#define BK 32
#define TM 8
#define TN 4
// threads = (BM/TM) * (BN/TN) = 16 * 16 = 256

// Scratch: folded weight slice W'[k][j] = W[k, 960+j] * (0.9 if 128<=k<960 else 1)
__device__ float g_W[N_SZ * O_SZ];
__device__ float g_bias[O_SZ];
__device__ int   g_act[O_SZ];

__global__ void prep_kernel(const float* __restrict__ W,
                            const float* __restrict__ bias,
                            const int* __restrict__ act) {
    int idx = blockIdx.x * blockDim.x + threadIdx.x;
    if (idx < N_SZ * O_SZ) {
        int k = idx >> 6;      // / 64
        int j = idx & 63;      // % 64
        float s = (k >= I_SZ && k < (N_SZ - O_SZ)) ? REFRACT : 1.0f;
        g_W[idx] = W[(size_t)k * N_SZ + (N_SZ - O_SZ) + j] * s;
    }
    if (idx < O_SZ) {
        g_bias[idx] = bias[(N_SZ - O_SZ) + idx];
        g_act[idx]  = act[(N_SZ - O_SZ) + idx];
    }
}

__device__ __forceinline__ float activate(float x, int a) {
    if (a == 0) return fmaxf(x, 0.0f);
    if (a == 1) return tanhf(x);
    if (a == 2) return 1.0f / (1.0f + expf(-x));
    return x;
}

__global__ __launch_bounds__(256)
void gemm_act_kernel(const float* __restrict__ prev,
                     const float* __restrict__ inp,
                     float* __restrict__ out) {
    // +4 pad keeps rows 16B-aligned (132 floats = 528B, 528 % 16 == 0) and conflict-free
    __shared__ float As[BK][BM + 4];   // A tile, stored K-major (transposed)
    __shared__ float Bs[BK][BN];       // W tile

    const int t  = threadIdx.x;
    const int m0 = blockIdx.x * BM;

    const int tx = t & 15;   // output-column group: cols tx*4 .. tx*4+3
    const int ty = t >> 4;   // row group: rows ty*8 .. ty*8+7

    float acc[TM][TN];
#pragma unroll
    for (int i = 0; i < TM; i++)
#pragma unroll
        for (int j = 0; j < TN; j++) acc[i][j] = 0.0f;

    // A-tile load mapping: 32 cols = 8 float4 per row; 8 threads per row, 32 rows/round
    const int a_row = t >> 3;        // 0..31
    const int a_c4  = (t & 7) * 4;   // 0,4,...,28

    for (int k0 = 0; k0 < N_SZ; k0 += BK) {
        const bool is_inp = (k0 < I_SZ);   // chunk-uniform: 128 % 32 == 0

        // ---- load A (states assembled on the fly; refractory folded into W) ----
#pragma unroll
        for (int rr = 0; rr < 4; rr++) {
            const int lr  = rr * 32 + a_row;       // local row 0..127
            const int row = m0 + lr;
            const int k   = k0 + a_c4;
            float4 v;
            if (is_inp) v = *(const float4*)(inp  + (size_t)row * I_SZ + k);
            else        v = *(const float4*)(prev + (size_t)row * N_SZ + k);
            As[a_c4 + 0][lr] = v.x;
            As[a_c4 + 1][lr] = v.y;
            As[a_c4 + 2][lr] = v.z;
            As[a_c4 + 3][lr] = v.w;
        }

        // ---- load B: g_W rows k0..k0+31 (2048 floats = 512 float4, 2 per thread) ----
        {
            const float4* src = (const float4*)(g_W + (size_t)k0 * O_SZ);
            float4* dst = (float4*)(&Bs[0][0]);
            dst[t]       = src[t];
            dst[t + 256] = src[t + 256];
        }
        __syncthreads();

        // ---- compute ----
#pragma unroll
        for (int kk = 0; kk < BK; kk++) {
            float4 a01 = *(const float4*)&As[kk][ty * TM + 0];
            float4 a23 = *(const float4*)&As[kk][ty * TM + 4];
            float4 bv  = *(const float4*)&Bs[kk][tx * TN];
            const float a[TM] = {a01.x, a01.y, a01.z, a01.w, a23.x, a23.y, a23.z, a23.w};
            const float b[TN] = {bv.x, bv.y, bv.z, bv.w};
#pragma unroll
            for (int i = 0; i < TM; i++)
#pragma unroll
                for (int j = 0; j < TN; j++)
                    acc[i][j] = fmaf(a[i], b[j], acc[i][j]);
        }
        __syncthreads();
    }

    // ---- epilogue: bias + heterogeneous activation, vectorized stores ----
    const int n0 = tx * TN;
    float bia[TN];
    int   aid[TN];
#pragma unroll
    for (int j = 0; j < TN; j++) { bia[j] = g_bias[n0 + j]; aid[j] = g_act[n0 + j]; }

#pragma unroll
    for (int i = 0; i < TM; i++) {
        const int row = m0 + ty * TM + i;
        float4 o;
        o.x = activate(acc[i][0] + bia[0], aid[0]);
        o.y = activate(acc[i][1] + bia[1], aid[1]);
        o.z = activate(acc[i][2] + bia[2], aid[2]);
        o.w = activate(acc[i][3] + bia[3], aid[3]);
        *(float4*)(out + (size_t)row * O_SZ + n0) = o;
    }
}

extern "C" void kernel_launch(void* const* d_in, const int* in_sizes, int n_in,
                              void* d_out, int out_size) {
    const float* prev = (const float*)d_in[0];   // [16384, 1024] f32
    const float* inp  = (const float*)d_in[1];   // [16384, 128]  f32
    const float* W    = (const float*)d_in[2];   // [1024, 1024]  f32
    const float* bias = (const float*)d_in[3];   // [1024]        f32
    const int*   act  = (const int*)d_in[4];     // [1024]        i32
    float* out = (float*)d_out;                  // [16384, 64]   f32

    prep_kernel<<<(N_SZ * O_SZ + 255) / 256, 256>>>(W, bias, act);
    gemm_act_kernel<<<B_SZ / BM, 256>>>(prev, inp, out);
}

// round 3
// speedup vs baseline: 2.1844x; 2.1844x over previous
#include <cuda_runtime.h>
#include <cuda_bf16.h>
#include <cstdint>
#include <math.h>

#define B_SZ 16384
#define N_SZ 1024
#define I_SZ 128
#define O_SZ 64
#define REFRACT 0.9f

#define BM 128
#define KC 64
#define NCHUNK 16
#define THREADS 256

// dynamic smem layout (base 1024-aligned)
#define OFF_AHI  0          // 128 rows x 128B (64 bf16)  = 16384
#define OFF_ALO  16384
#define OFF_BHI  32768      // 64 rows x 128B             = 8192
#define OFF_BLO  40960
#define OFF_BIAS 49152      // f32[64]
#define OFF_ACT  49408      // i32[64]
#define SMEM_TOTAL 49664

// Prepped weights: W'[n][k] (K-major, transposed), refractory folded, bf16 hi/lo
__device__ __align__(16) unsigned short g_Whi[O_SZ * N_SZ];
__device__ __align__(16) unsigned short g_Wlo[O_SZ * N_SZ];
__device__ float g_bias[O_SZ];
__device__ int   g_act[O_SZ];

// ---------------- helpers ----------------
__device__ __forceinline__ uint32_t smem_u32(const void* p) {
    uint32_t a;
    asm("{ .reg .u64 t; cvta.to.shared.u64 t, %1; cvt.u32.u64 %0, t; }"
        : "=r"(a) : "l"(p));
    return a;
}
// returns packed bf16x2: low half = bf16(lo), high half = bf16(hi)
__device__ __forceinline__ uint32_t pack_bf16(float lo, float hi) {
    uint32_t r;
    asm("cvt.rn.bf16x2.f32 %0, %1, %2;" : "=r"(r) : "f"(hi), "f"(lo));
    return r;
}
__device__ __forceinline__ uint32_t swz(uint32_t off) {
    return off ^ ((off >> 3) & 0x70);
}
__device__ __forceinline__ void ldsm4(uint32_t* r, uint32_t addr) {
    asm volatile("ldmatrix.sync.aligned.m8n8.x4.shared.b16 {%0,%1,%2,%3}, [%4];"
                 : "=r"(r[0]), "=r"(r[1]), "=r"(r[2]), "=r"(r[3]) : "r"(addr));
}
__device__ __forceinline__ void mma16816(float* c, const uint32_t* a,
                                         uint32_t b0, uint32_t b1) {
    asm volatile(
        "mma.sync.aligned.m16n8k16.row.col.f32.bf16.bf16.f32 "
        "{%0,%1,%2,%3}, {%4,%5,%6,%7}, {%8,%9}, {%0,%1,%2,%3};"
        : "+f"(c[0]), "+f"(c[1]), "+f"(c[2]), "+f"(c[3])
        : "r"(a[0]), "r"(a[1]), "r"(a[2]), "r"(a[3]), "r"(b0), "r"(b1));
}
__device__ __forceinline__ float activate(float x, int a) {
    if (a == 0) return fmaxf(x, 0.0f);
    if (a == 1) return tanhf(x);
    if (a == 2) return 1.0f / (1.0f + expf(-x));
    return x;
}

// ---------------- prep: fold refractory, transpose, bf16 split ----------------
__global__ void prep_kernel(const float* __restrict__ W,
                            const float* __restrict__ bias,
                            const int* __restrict__ act) {
    int idx = blockIdx.x * blockDim.x + threadIdx.x;   // 65536
    if (idx < O_SZ * N_SZ) {
        int k = idx >> 6;
        int n = idx & 63;
        float s = (k >= I_SZ && k < (N_SZ - O_SZ)) ? REFRACT : 1.0f;
        float w = W[(size_t)k * N_SZ + (N_SZ - O_SZ) + n] * s;
        uint32_t hp = pack_bf16(w, 0.0f);
        float hf = __uint_as_float(hp << 16);
        uint32_t lp = pack_bf16(w - hf, 0.0f);
        g_Whi[n * N_SZ + k] = (unsigned short)(hp & 0xFFFF);
        g_Wlo[n * N_SZ + k] = (unsigned short)(lp & 0xFFFF);
    }
    if (idx < O_SZ) {
        g_bias[idx] = bias[(N_SZ - O_SZ) + idx];
        g_act[idx]  = act[(N_SZ - O_SZ) + idx];
    }
}

// ---------------- chunk load (gmem -> regs) ----------------
__device__ __forceinline__ void load_chunk(int i, int t, int m0,
                                           const float* __restrict__ prev,
                                           const float* __restrict__ inp,
                                           float4 (&a)[8], uint4 (&b)[4]) {
    const int k0 = i * KC;
    const int rr = t >> 3;           // 0..31
    const int kf = (t & 7) * 8;      // float offset within chunk
    if (k0 < I_SZ) {
#pragma unroll
        for (int p = 0; p < 4; p++) {
            const float* s = inp + (size_t)(m0 + p * 32 + rr) * I_SZ + k0 + kf;
            a[2 * p]     = ((const float4*)s)[0];
            a[2 * p + 1] = ((const float4*)s)[1];
        }
    } else {
#pragma unroll
        for (int p = 0; p < 4; p++) {
            const float* s = prev + (size_t)(m0 + p * 32 + rr) * N_SZ + k0 + kf;
            a[2 * p]     = ((const float4*)s)[0];
            a[2 * p + 1] = ((const float4*)s)[1];
        }
    }
#pragma unroll
    for (int p = 0; p < 2; p++) {
        const int slot = p * 256 + t;          // 0..511
        const int n = slot >> 3, u = slot & 7;
        const size_t byt = (size_t)n * 2048 + (size_t)k0 * 2 + (size_t)u * 16;
        b[p]     = *(const uint4*)((const char*)g_Whi + byt);
        b[p + 2] = *(const uint4*)((const char*)g_Wlo + byt);
    }
}

// ---------------- chunk store (regs -> smem, bf16 split + swizzle) ----------------
__device__ __forceinline__ void store_chunk(char* smem, int t,
                                            const float4 (&a)[8], const uint4 (&b)[4]) {
#pragma unroll
    for (int p = 0; p < 4; p++) {
        const int r = p * 32 + (t >> 3);
        const int u = t & 7;
        const uint32_t off = swz((uint32_t)(r * 128 + u * 16));
        const float4 v0 = a[2 * p], v1 = a[2 * p + 1];
        const uint32_t h0 = pack_bf16(v0.x, v0.y);
        const uint32_t h1 = pack_bf16(v0.z, v0.w);
        const uint32_t h2 = pack_bf16(v1.x, v1.y);
        const uint32_t h3 = pack_bf16(v1.z, v1.w);
        const float r0 = v0.x - __uint_as_float(h0 << 16);
        const float r1 = v0.y - __uint_as_float(h0 & 0xFFFF0000u);
        const float r2 = v0.z - __uint_as_float(h1 << 16);
        const float r3 = v0.w - __uint_as_float(h1 & 0xFFFF0000u);
        const float r4 = v1.x - __uint_as_float(h2 << 16);
        const float r5 = v1.y - __uint_as_float(h2 & 0xFFFF0000u);
        const float r6 = v1.z - __uint_as_float(h3 << 16);
        const float r7 = v1.w - __uint_as_float(h3 & 0xFFFF0000u);
        const uint32_t l0 = pack_bf16(r0, r1);
        const uint32_t l1 = pack_bf16(r2, r3);
        const uint32_t l2 = pack_bf16(r4, r5);
        const uint32_t l3 = pack_bf16(r6, r7);
        *(uint4*)(smem + OFF_AHI + off) = make_uint4(h0, h1, h2, h3);
        *(uint4*)(smem + OFF_ALO + off) = make_uint4(l0, l1, l2, l3);
    }
#pragma unroll
    for (int p = 0; p < 2; p++) {
        const int slot = p * 256 + t;
        const int n = slot >> 3, u = slot & 7;
        const uint32_t off = swz((uint32_t)(n * 128 + u * 16));
        *(uint4*)(smem + OFF_BHI + off) = b[p];
        *(uint4*)(smem + OFF_BLO + off) = b[p + 2];
    }
}

// ---------------- main kernel ----------------
__global__ __launch_bounds__(THREADS, 1)
void mma_kernel(const float* __restrict__ prev,
                const float* __restrict__ inp,
                float* __restrict__ out) {
    extern __shared__ __align__(1024) char smem[];
    const uint32_t sb = smem_u32(smem);
    const int t = threadIdx.x;
    const int lane = t & 31, wid = t >> 5;
    const int m0 = blockIdx.x * BM;

    if (t < O_SZ) {
        ((float*)(smem + OFF_BIAS))[t] = g_bias[t];
        ((int*)(smem + OFF_ACT))[t]    = g_act[t];
    }

    float acc[8][4];
#pragma unroll
    for (int j = 0; j < 8; j++)
#pragma unroll
        for (int c = 0; c < 4; c++) acc[j][c] = 0.0f;

    // ldmatrix lane geometry
    const int lrow = lane & 7, seg = lane >> 3;
    const int arow = wid * 16 + lrow + ((seg & 1) << 3);
    const int akb0 = (seg & 2) << 3;          // 0 or 16 bytes
    const int brow = lrow + ((seg & 2) << 2); // +8 for seg>=2
    const int bkb0 = (seg & 1) << 4;          // 0 or 16 bytes

    float4 A[8];
    uint4  Bv[4];
    load_chunk(0, t, m0, prev, inp, A, Bv);

    for (int i = 0; i < NCHUNK; i++) {
        store_chunk(smem, t, A, Bv);
        __syncthreads();
        if (i + 1 < NCHUNK) load_chunk(i + 1, t, m0, prev, inp, A, Bv);

#pragma unroll
        for (int s = 0; s < 4; s++) {
            uint32_t ah[4], al[4];
            const uint32_t aoff = swz((uint32_t)(arow * 128 + s * 32 + akb0));
            ldsm4(ah, sb + OFF_AHI + aoff);
            ldsm4(al, sb + OFF_ALO + aoff);
#pragma unroll
            for (int j = 0; j < 4; j++) {
                uint32_t bh[4], bl[4];
                const uint32_t boff =
                    swz((uint32_t)((16 * j + brow) * 128 + s * 32 + bkb0));
                ldsm4(bh, sb + OFF_BHI + boff);
                ldsm4(bl, sb + OFF_BLO + boff);
                mma16816(acc[2 * j],     ah, bh[0], bh[1]);
                mma16816(acc[2 * j + 1], ah, bh[2], bh[3]);
                mma16816(acc[2 * j],     ah, bl[0], bl[1]);
                mma16816(acc[2 * j + 1], ah, bl[2], bl[3]);
                mma16816(acc[2 * j],     al, bh[0], bh[1]);
                mma16816(acc[2 * j + 1], al, bh[2], bh[3]);
            }
        }
        __syncthreads();
    }

    // ---------------- epilogue ----------------
    const float* sbias = (const float*)(smem + OFF_BIAS);
    const int*   sact  = (const int*)(smem + OFF_ACT);
    const int g = lane >> 2, q = lane & 3;
    const int row0 = m0 + wid * 16 + g;
#pragma unroll
    for (int j = 0; j < 8; j++) {
        const int col = j * 8 + q * 2;
        const float b0 = sbias[col], b1 = sbias[col + 1];
        const int   i0 = sact[col],  i1 = sact[col + 1];
        float2 v0, v1;
        v0.x = activate(acc[j][0] + b0, i0);
        v0.y = activate(acc[j][1] + b1, i1);
        v1.x = activate(acc[j][2] + b0, i0);
        v1.y = activate(acc[j][3] + b1, i1);
        *(float2*)(out + (size_t)row0 * O_SZ + col)       = v0;
        *(float2*)(out + (size_t)(row0 + 8) * O_SZ + col) = v1;
    }
}

extern "C" void kernel_launch(void* const* d_in, const int* in_sizes, int n_in,
                              void* d_out, int out_size) {
    const float* prev = (const float*)d_in[0];   // [16384,1024] f32
    const float* inp  = (const float*)d_in[1];   // [16384,128]  f32
    const float* W    = (const float*)d_in[2];   // [1024,1024]  f32
    const float* bias = (const float*)d_in[3];   // [1024]       f32
    const int*   act  = (const int*)d_in[4];     // [1024]       i32
    float* out = (float*)d_out;                  // [16384,64]   f32

    cudaFuncSetAttribute(mma_kernel,
                         cudaFuncAttributeMaxDynamicSharedMemorySize, SMEM_TOTAL);

    prep_kernel<<<(O_SZ * N_SZ + 255) / 256, 256>>>(W, bias, act);
    mma_kernel<<<B_SZ / BM, THREADS, SMEM_TOTAL>>>(prev, inp, out);
}